// round 15
// baseline (speedup 1.0000x reference)
#include <cuda_runtime.h>
#include <math.h>

#define BN_EPS 1e-5f
#define NB 2
#define NC 128
#define NPT 4096
#define KK 20
#define CHH 64
#define CDD 16

// ---------------- device scratch (no allocations allowed) ----------------
__device__ int   d_idx[NB * NPT * KK];
__device__ float d_P[NB * NPT * NC];       // [b][n][c]  c<64: xyz-half, c>=64: feat-half
__device__ float d_Q[NB * NPT * NC];
__device__ float d_fenc[NB * NPT * NC];    // [b][n][c]
__device__ float d_f1[NB * NPT * CDD];     // [b][n][o]
__device__ float d_f2[NB * NPT * CDD];
__device__ float d_fsp[NPT];
__device__ float d_fchpart[512 * CDD];

// ---------------- KNN: warp-shared top-20, 2 rows/warp, 3-FMA distance ------
// Rank by d' = |p_j|^2 - 2<p_j, c> (the reference's own algebra: monotone-
// equivalent to ||p_j - c||^2, center term constant per row). Points packed
// as (x, y, z, |p|^2) float4 in 64KB dynamic smem -> 1 LDS128 + 3 FMA per
// candidate-row instead of 2 LDS + 6 ops. One full-cloud scan per row keeps
// acceptance count at the k*ln(N/k) minimum (R12 lesson).
__global__ void __launch_bounds__(256) knn_kernel(const float* __restrict__ xyz)
{
    extern __shared__ float4 sp[];   // [NPT] = 64KB dynamic

    int b = blockIdx.y;
    const float* base = xyz + b * 3 * NPT;
    for (int i = threadIdx.x; i < NPT; i += 256) {
        float x = base[i], y = base[NPT + i], z = base[2 * NPT + i];
        sp[i] = make_float4(x, y, z, fmaf(x, x, fmaf(y, y, z * z)));
    }
    __syncthreads();

    int warp = threadIdx.x >> 5;
    int lane = threadIdx.x & 31;
    const unsigned FULL = 0xffffffffu;
    int n0 = (blockIdx.x * 8 + warp) * 2;

    float m2x[2], m2y[2], m2z[2], ld[2], worst[2];
    int   lj[2];
    #pragma unroll
    for (int r = 0; r < 2; ++r) {
        float4 c = sp[n0 + r];
        m2x[r] = -2.f * c.x; m2y[r] = -2.f * c.y; m2z[r] = -2.f * c.z;
        ld[r] = 1e30f; lj[r] = 0; worst[r] = 1e30f;
    }

    for (int j0 = 0; j0 < NPT; j0 += 32) {
        float4 pj = sp[j0 + lane];
        float d[2];
        #pragma unroll
        for (int r = 0; r < 2; ++r)
            d[r] = fmaf(m2x[r], pj.x, fmaf(m2y[r], pj.y, fmaf(m2z[r], pj.z, pj.w)));
        #pragma unroll
        for (int r = 0; r < 2; ++r) {
            unsigned mask = __ballot_sync(FULL, d[r] < worst[r]);
            if (mask) {
                do {
                    int src = __ffs(mask) - 1;
                    mask &= mask - 1;
                    float v = __shfl_sync(FULL, d[r], src);
                    bool gt = (lane < KK) && (ld[r] > v);
                    unsigned gm = __ballot_sync(FULL, gt);
                    if (gm) {                       // v < current 20th
                        int pos = __ffs(gm) - 1;
                        float ud = __shfl_up_sync(FULL, ld[r], 1);
                        int   uj = __shfl_up_sync(FULL, lj[r], 1);
                        if (lane > pos && lane < KK) { ld[r] = ud; lj[r] = uj; }
                        if (lane == pos)             { ld[r] = v;  lj[r] = j0 + src; }
                    }
                } while (mask);
                worst[r] = __shfl_sync(FULL, ld[r], KK - 1);
            }
        }
    }

    #pragma unroll
    for (int r = 0; r < 2; ++r)
        if (lane < KK)
            d_idx[(b * NPT + n0 + r) * KK + lane] = lj[r];
}

// ---------------- PQ: per-point projections, BN folded inline ----------------
__global__ void __launch_bounds__(128) pq_kernel(const float* __restrict__ xyz,
                                                 const float* __restrict__ features,
                                                 const float* __restrict__ w_mlp1,
                                                 const float* __restrict__ b_mlp1,
                                                 const float* __restrict__ g1,
                                                 const float* __restrict__ be1,
                                                 const float* __restrict__ m1,
                                                 const float* __restrict__ v1,
                                                 const float* __restrict__ w_mlp2,
                                                 const float* __restrict__ b_mlp2,
                                                 const float* __restrict__ g2,
                                                 const float* __restrict__ be2,
                                                 const float* __restrict__ m2,
                                                 const float* __restrict__ v2)
{
    __shared__ __align__(16) float s_f[NC * 16];  // [j][p]
    __shared__ float s_w[64 * 129];               // [j_local][cout] padded
    __shared__ float s_x[3 * 16];                 // [j][p]
    __shared__ float s_s2[64];                    // folded BN2 scale
    int b = blockIdx.y;
    int n0 = blockIdx.x * 16;
    int tid = threadIdx.x;

    for (int i = tid; i < NC * 16; i += 128) {
        int j = i >> 4, p = i & 15;
        s_f[i] = features[b * NC * NPT + j * NPT + n0 + p];
    }
    if (tid < 48) {
        int j = tid >> 4, p = tid & 15;
        s_x[tid] = xyz[b * 3 * NPT + j * NPT + n0 + p];
    }
    if (tid < 64)
        s_s2[tid] = g2[tid] * rsqrtf(v2[tid] + BN_EPS);

    float acc[16];
    #pragma unroll
    for (int p = 0; p < 16; ++p) acc[p] = 0.f;
    int cout = tid;

    for (int jc = 0; jc < NC; jc += 64) {
        __syncthreads();
        for (int i = tid; i < 64 * 128; i += 128) {
            int jl = i & 63, co = i >> 6;
            int cc = (co < 64) ? co : (co - 64);
            float wa = w_mlp2[cc * 256 + jc + jl];
            float w;
            if (co < 64) {
                w = s_s2[cc] * wa;
            } else {
                float wb = w_mlp2[cc * 256 + 128 + jc + jl];
                w = s_s2[cc] * (wb - wa);
            }
            s_w[jl * 129 + co] = w;
        }
        __syncthreads();
        #pragma unroll 4
        for (int jl = 0; jl < 64; ++jl) {
            float w = s_w[jl * 129 + cout];
            const float4* f4 = (const float4*)(s_f + (jc + jl) * 16);
            float fv[16];
            *(float4*)(fv + 0)  = f4[0];
            *(float4*)(fv + 4)  = f4[1];
            *(float4*)(fv + 8)  = f4[2];
            *(float4*)(fv + 12) = f4[3];
            #pragma unroll
            for (int p = 0; p < 16; ++p) acc[p] = fmaf(w, fv[p], acc[p]);
        }
    }

    if (cout < 64) {
        #pragma unroll
        for (int p = 0; p < 16; ++p)
            d_P[(b * NPT + n0 + p) * NC + 64 + cout] = acc[p];
        float s1 = g1[cout] * rsqrtf(v1[cout] + BN_EPS);
        float w0 = s1 * w_mlp1[cout * 6 + 0];
        float w1 = s1 * w_mlp1[cout * 6 + 1];
        float w2 = s1 * w_mlp1[cout * 6 + 2];
        #pragma unroll
        for (int p = 0; p < 16; ++p)
            d_P[(b * NPT + n0 + p) * NC + cout] =
                fmaf(w0, s_x[p], fmaf(w1, s_x[16 + p], w2 * s_x[32 + p]));
    } else {
        int cq = cout - 64;
        float s2v = s_s2[cq];
        float bb = s2v * b_mlp2[cq] + (be2[cq] - m2[cq] * s2v);
        #pragma unroll
        for (int p = 0; p < 16; ++p)
            d_Q[(b * NPT + n0 + p) * NC + 64 + cq] = acc[p] + bb;
        float s1 = g1[cq] * rsqrtf(v1[cq] + BN_EPS);
        float w0 = s1 * (w_mlp1[cq * 6 + 3] - w_mlp1[cq * 6 + 0]);
        float w1 = s1 * (w_mlp1[cq * 6 + 4] - w_mlp1[cq * 6 + 1]);
        float w2 = s1 * (w_mlp1[cq * 6 + 5] - w_mlp1[cq * 6 + 2]);
        float b1 = s1 * b_mlp1[cq] + (be1[cq] - m1[cq] * s1);
        #pragma unroll
        for (int p = 0; p < 16; ++p)
            d_Q[(b * NPT + n0 + p) * NC + cq] =
                fmaf(w0, s_x[p], fmaf(w1, s_x[16 + p], fmaf(w2, s_x[32 + p], b1)));
    }
}

// ---------------- fused fenc + down: gather/max/relu then down-proj ----------
__global__ void __launch_bounds__(256) fenc_down_kernel(const float* __restrict__ wd1,
                                                        const float* __restrict__ wd2)
{
    __shared__ __align__(16) float s_fe[8 * NC];   // 4KB
    __shared__ __align__(16) float s_w[32 * 132];  // padded to 132 for float4
    __shared__ float s_part[CDD * 9];
    __shared__ int s_idx[8 * KK];
    int b = blockIdx.y, n0 = blockIdx.x * 8, tid = threadIdx.x;

    for (int i = tid; i < 8 * KK; i += 256)
        s_idx[i] = d_idx[(b * NPT + n0) * KK + i] * NC;   // pre-scaled
    for (int i = tid; i < 32 * NC; i += 256) {
        int o = i >> 7, c = i & 127;
        float w = (o < 16) ? wd1[o * NC + c] : wd2[(o - 16) * NC + c];
        s_w[o * 132 + c] = w;
    }
    __syncthreads();

    // ---- gather phase: 4 points per thread, 4 independent max chains ----
    {
        int c = tid & 127, ph = tid >> 7;
        const float* Pb = d_P + b * NPT * NC + c;
        float m[4];
        #pragma unroll
        for (int r = 0; r < 4; ++r) m[r] = -1e30f;
        #pragma unroll
        for (int kb = 0; kb < KK; kb += 5) {
            float v[4][5];
            #pragma unroll
            for (int r = 0; r < 4; ++r)
                #pragma unroll
                for (int kk = 0; kk < 5; ++kk)
                    v[r][kk] = Pb[s_idx[(ph * 4 + r) * KK + kb + kk]];
            #pragma unroll
            for (int r = 0; r < 4; ++r)
                #pragma unroll
                for (int kk = 0; kk < 5; ++kk)
                    m[r] = fmaxf(m[r], v[r][kk]);
        }
        #pragma unroll
        for (int r = 0; r < 4; ++r) {
            int p = ph * 4 + r;
            int n = n0 + p;
            float q = d_Q[(b * NPT + n) * NC + c];
            float fe = fmaxf(q + m[r], 0.f);
            s_fe[p * NC + c] = fe;
            d_fenc[(b * NPT + n) * NC + c] = fe;
        }
    }
    __syncthreads();

    // ---- down phase: float4 LDS, same arithmetic order as scalar ----
    int o = tid & 31, p = tid >> 5;
    const float4* wr = (const float4*)(s_w + o * 132);
    const float4* fr = (const float4*)(s_fe + p * NC);
    float a = 0.f;
    #pragma unroll 8
    for (int c4 = 0; c4 < 32; ++c4) {
        float4 w4 = wr[c4];
        float4 f4 = fr[c4];
        a = fmaf(w4.x, f4.x, a);
        a = fmaf(w4.y, f4.y, a);
        a = fmaf(w4.z, f4.z, a);
        a = fmaf(w4.w, f4.w, a);
    }
    a = fmaxf(a, 0.f);
    int n = n0 + p;
    if (o < 16) {
        d_f1[(b * NPT + n) * CDD + o] = a;
        if (b == 0) s_part[o * 9 + p] = a;
    } else {
        d_f2[(b * NPT + n) * CDD + (o - 16)] = a;
    }
    if (b == 0) {
        float v = (o >= 16) ? a : 0.f;
        #pragma unroll
        for (int off = 16; off > 0; off >>= 1)
            v += __shfl_down_sync(0xffffffffu, v, off);
        if (o == 0) d_fsp[n] = v * (1.f / 16.f);
        __syncthreads();
        if (tid < CDD) {
            float s = 0.f;
            #pragma unroll
            for (int p2 = 0; p2 < 8; ++p2) s += s_part[tid * 9 + p2];
            d_fchpart[blockIdx.x * CDD + tid] = s;
        }
    }
}

// ---------------- final: vectorized fch reduce, cross-term, up-proj, mish ----
__global__ void __launch_bounds__(256) final_kernel(float* __restrict__ out,
                                                    const float* __restrict__ w_up,
                                                    const float* __restrict__ b_up,
                                                    const float* __restrict__ gu,
                                                    const float* __restrict__ beu,
                                                    const float* __restrict__ mu,
                                                    const float* __restrict__ vu)
{
    __shared__ float s_v[16 * 17];
    __shared__ float s_o[128 * 17];
    __shared__ float s_red[CDD][68];
    __shared__ float s_fch[CDD];
    int b = blockIdx.y, n0 = blockIdx.x * 16, tid = threadIdx.x;

    // inline deterministic f_channel reduction, float4 loads (identical in
    // every block -> deterministic). Thread = (o-quad, 8 block-rows).
    {
        int q = tid & 3, ch = tid >> 2;          // quad 0..3, chunk 0..63
        const float4* fp4 = (const float4*)d_fchpart;  // [512][4]
        float4 acc = make_float4(0.f, 0.f, 0.f, 0.f);
        #pragma unroll
        for (int i = 0; i < 8; ++i) {
            float4 v = fp4[(ch * 8 + i) * 4 + q];
            acc.x += v.x; acc.y += v.y; acc.z += v.z; acc.w += v.w;
        }
        s_red[q * 4 + 0][ch] = acc.x;
        s_red[q * 4 + 1][ch] = acc.y;
        s_red[q * 4 + 2][ch] = acc.z;
        s_red[q * 4 + 3][ch] = acc.w;
    }
    __syncthreads();
    if (tid < CDD) {
        float sum = 0.f;
        #pragma unroll 8
        for (int c2 = 0; c2 < 64; ++c2) sum += s_red[tid][c2];
        s_fch[tid] = sum * (1.f / (float)NPT);
    }
    __syncthreads();

    {
        int o = tid & 15, p = tid >> 4;    // 256 threads = 16x16 exactly
        int n = n0 + p;
        float f1v = d_f1[(b * NPT + n) * CDD + o];
        float f2v = d_f2[(b * NPT + n) * CDD + o];
        float cross = sqrtf(fmaf(s_fch[o], d_fsp[n], 1e-12f));
        s_v[o * 17 + p] = cross + f1v + f2v;
    }
    __syncthreads();

    int c = tid & 127, ph = tid >> 7;
    float su = gu[c] * rsqrtf(vu[c] + BN_EPS);
    float w16[16];
    #pragma unroll
    for (int o = 0; o < 16; ++o) w16[o] = su * w_up[c * CDD + o];
    float bup = su * b_up[c] + (beu[c] - mu[c] * su);

    #pragma unroll
    for (int p = ph * 8; p < ph * 8 + 8; ++p) {
        float a = bup;
        #pragma unroll
        for (int o = 0; o < 16; ++o) a = fmaf(w16[o], s_v[o * 17 + p], a);
        float U = fmaxf(a, 0.f);
        float fe = d_fenc[(b * NPT + n0 + p) * NC + c];
        float x = fe - U;
        float e = __expf(x);
        float u = fmaf(e, e, e + e);            // e^2 + 2e
        float t = (x > 30.f) ? 1.f : __fdividef(u, u + 2.f);
        s_o[c * 17 + p] = x * t;
    }
    __syncthreads();

    for (int i = tid; i < 128 * 16; i += 256) {
        int cc = i >> 4, p = i & 15;
        out[b * NC * NPT + cc * NPT + n0 + p] = s_o[cc * 17 + p];
    }
}

// ---------------- launch ----------------
extern "C" void kernel_launch(void* const* d_in, const int* in_sizes, int n_in,
                              void* d_out, int out_size)
{
    const float* xyz      = (const float*)d_in[0];
    const float* features = (const float*)d_in[1];
    const float* w_mlp1   = (const float*)d_in[2];
    const float* b_mlp1   = (const float*)d_in[3];
    const float* g1       = (const float*)d_in[4];
    const float* be1      = (const float*)d_in[5];
    const float* m1       = (const float*)d_in[6];
    const float* v1       = (const float*)d_in[7];
    const float* w_mlp2   = (const float*)d_in[8];
    const float* b_mlp2   = (const float*)d_in[9];
    const float* g2       = (const float*)d_in[10];
    const float* be2      = (const float*)d_in[11];
    const float* m2       = (const float*)d_in[12];
    const float* v2       = (const float*)d_in[13];
    const float* w_down1  = (const float*)d_in[14];
    const float* w_down2  = (const float*)d_in[15];
    const float* w_up     = (const float*)d_in[16];
    const float* b_up     = (const float*)d_in[17];
    const float* gu       = (const float*)d_in[18];
    const float* beu      = (const float*)d_in[19];
    const float* mu       = (const float*)d_in[20];
    const float* vu       = (const float*)d_in[21];
    // d_in[22] = k (always 20 for this problem; compiled in)

    const int KNN_SMEM = NPT * 16;   // 64KB float4
    cudaFuncSetAttribute(knn_kernel,
                         cudaFuncAttributeMaxDynamicSharedMemorySize, KNN_SMEM);

    knn_kernel<<<dim3(NPT / 16, NB), 256, KNN_SMEM>>>(xyz);
    pq_kernel<<<dim3(NPT / 16, NB), 128>>>(xyz, features,
                                           w_mlp1, b_mlp1, g1, be1, m1, v1,
                                           w_mlp2, b_mlp2, g2, be2, m2, v2);
    fenc_down_kernel<<<dim3(NPT / 8, NB), 256>>>(w_down1, w_down2);
    final_kernel<<<dim3(NPT / 16, NB), 256>>>((float*)d_out,
                                              w_up, b_up, gu, beu, mu, vu);
}

// round 16
// speedup vs baseline: 1.1892x; 1.1892x over previous
#include <cuda_runtime.h>
#include <math.h>

#define BN_EPS 1e-5f
#define NB 2
#define NC 128
#define NPT 4096
#define KK 20
#define CHH 64
#define CDD 16

// ---------------- device scratch (no allocations allowed) ----------------
__device__ int   d_idx[NB * NPT * KK];
__device__ float d_P[NB * NPT * NC];       // [b][n][c]  c<64: xyz-half, c>=64: feat-half
__device__ float d_Q[NB * NPT * NC];
__device__ float d_fenc[NB * NPT * NC];    // [b][n][c]
__device__ float d_f1[NB * NPT * CDD];     // [b][n][o]
__device__ float d_f2[NB * NPT * CDD];
__device__ float d_fsp[NPT];
__device__ float d_fchpart[512 * CDD];

// ---------------- KNN: warp-shared top-20, 2 rows per warp (R14 version) ----
// Best-measured config: 48KB static smem -> 4 CTAs/SM cap, grid 512 in one
// wave, 7 warps/SMSP hiding the serialized insertion chain. (R15's 64KB
// float4 layout cut the CTA cap to 3 and regressed: occupancy > op-count
// for this latency-bound kernel.)
__global__ void __launch_bounds__(256) knn_kernel(const float* __restrict__ xyz)
{
    __shared__ float2 sxy[NPT];   // 32KB
    __shared__ float  szz[NPT];   // 16KB

    int b = blockIdx.y;
    const float* base = xyz + b * 3 * NPT;
    for (int i = threadIdx.x; i < NPT; i += 256) {
        sxy[i] = make_float2(base[i], base[NPT + i]);
        szz[i] = base[2 * NPT + i];
    }
    __syncthreads();

    int warp = threadIdx.x >> 5;
    int lane = threadIdx.x & 31;
    const unsigned FULL = 0xffffffffu;
    int n0 = (blockIdx.x * 8 + warp) * 2;

    float xn[2], yn[2], zn[2], ld[2], worst[2];
    int   lj[2];
    #pragma unroll
    for (int r = 0; r < 2; ++r) {
        float2 c = sxy[n0 + r];
        xn[r] = c.x; yn[r] = c.y; zn[r] = szz[n0 + r];
        ld[r] = 1e30f; lj[r] = 0; worst[r] = 1e30f;
    }

    for (int j0 = 0; j0 < NPT; j0 += 32) {
        float2 pxy = sxy[j0 + lane];
        float  pz  = szz[j0 + lane];
        float d[2];
        #pragma unroll
        for (int r = 0; r < 2; ++r) {
            float dx = pxy.x - xn[r];
            float dy = pxy.y - yn[r];
            float dz = pz    - zn[r];
            d[r] = fmaf(dx, dx, fmaf(dy, dy, dz * dz));
        }
        #pragma unroll
        for (int r = 0; r < 2; ++r) {
            unsigned mask = __ballot_sync(FULL, d[r] < worst[r]);
            if (mask) {
                do {
                    int src = __ffs(mask) - 1;
                    mask &= mask - 1;
                    float v = __shfl_sync(FULL, d[r], src);
                    bool gt = (lane < KK) && (ld[r] > v);
                    unsigned gm = __ballot_sync(FULL, gt);
                    if (gm) {                       // v < current 20th
                        int pos = __ffs(gm) - 1;
                        float ud = __shfl_up_sync(FULL, ld[r], 1);
                        int   uj = __shfl_up_sync(FULL, lj[r], 1);
                        if (lane > pos && lane < KK) { ld[r] = ud; lj[r] = uj; }
                        if (lane == pos)             { ld[r] = v;  lj[r] = j0 + src; }
                    }
                } while (mask);
                worst[r] = __shfl_sync(FULL, ld[r], KK - 1);
            }
        }
    }

    #pragma unroll
    for (int r = 0; r < 2; ++r)
        if (lane < KK)
            d_idx[(b * NPT + n0 + r) * KK + lane] = lj[r];
}

// ---------------- PQ: per-point projections, BN folded inline ----------------
__global__ void __launch_bounds__(128) pq_kernel(const float* __restrict__ xyz,
                                                 const float* __restrict__ features,
                                                 const float* __restrict__ w_mlp1,
                                                 const float* __restrict__ b_mlp1,
                                                 const float* __restrict__ g1,
                                                 const float* __restrict__ be1,
                                                 const float* __restrict__ m1,
                                                 const float* __restrict__ v1,
                                                 const float* __restrict__ w_mlp2,
                                                 const float* __restrict__ b_mlp2,
                                                 const float* __restrict__ g2,
                                                 const float* __restrict__ be2,
                                                 const float* __restrict__ m2,
                                                 const float* __restrict__ v2)
{
    __shared__ __align__(16) float s_f[NC * 16];  // [j][p]
    __shared__ float s_w[64 * 129];               // [j_local][cout] padded
    __shared__ float s_x[3 * 16];                 // [j][p]
    __shared__ float s_s2[64];                    // folded BN2 scale
    int b = blockIdx.y;
    int n0 = blockIdx.x * 16;
    int tid = threadIdx.x;

    for (int i = tid; i < NC * 16; i += 128) {
        int j = i >> 4, p = i & 15;
        s_f[i] = features[b * NC * NPT + j * NPT + n0 + p];
    }
    if (tid < 48) {
        int j = tid >> 4, p = tid & 15;
        s_x[tid] = xyz[b * 3 * NPT + j * NPT + n0 + p];
    }
    if (tid < 64)
        s_s2[tid] = g2[tid] * rsqrtf(v2[tid] + BN_EPS);

    float acc[16];
    #pragma unroll
    for (int p = 0; p < 16; ++p) acc[p] = 0.f;
    int cout = tid;

    for (int jc = 0; jc < NC; jc += 64) {
        __syncthreads();
        for (int i = tid; i < 64 * 128; i += 128) {
            int jl = i & 63, co = i >> 6;
            int cc = (co < 64) ? co : (co - 64);
            float wa = w_mlp2[cc * 256 + jc + jl];
            float w;
            if (co < 64) {
                w = s_s2[cc] * wa;
            } else {
                float wb = w_mlp2[cc * 256 + 128 + jc + jl];
                w = s_s2[cc] * (wb - wa);
            }
            s_w[jl * 129 + co] = w;
        }
        __syncthreads();
        #pragma unroll 4
        for (int jl = 0; jl < 64; ++jl) {
            float w = s_w[jl * 129 + cout];
            const float4* f4 = (const float4*)(s_f + (jc + jl) * 16);
            float fv[16];
            *(float4*)(fv + 0)  = f4[0];
            *(float4*)(fv + 4)  = f4[1];
            *(float4*)(fv + 8)  = f4[2];
            *(float4*)(fv + 12) = f4[3];
            #pragma unroll
            for (int p = 0; p < 16; ++p) acc[p] = fmaf(w, fv[p], acc[p]);
        }
    }

    if (cout < 64) {
        #pragma unroll
        for (int p = 0; p < 16; ++p)
            d_P[(b * NPT + n0 + p) * NC + 64 + cout] = acc[p];
        float s1 = g1[cout] * rsqrtf(v1[cout] + BN_EPS);
        float w0 = s1 * w_mlp1[cout * 6 + 0];
        float w1 = s1 * w_mlp1[cout * 6 + 1];
        float w2 = s1 * w_mlp1[cout * 6 + 2];
        #pragma unroll
        for (int p = 0; p < 16; ++p)
            d_P[(b * NPT + n0 + p) * NC + cout] =
                fmaf(w0, s_x[p], fmaf(w1, s_x[16 + p], w2 * s_x[32 + p]));
    } else {
        int cq = cout - 64;
        float s2v = s_s2[cq];
        float bb = s2v * b_mlp2[cq] + (be2[cq] - m2[cq] * s2v);
        #pragma unroll
        for (int p = 0; p < 16; ++p)
            d_Q[(b * NPT + n0 + p) * NC + 64 + cq] = acc[p] + bb;
        float s1 = g1[cq] * rsqrtf(v1[cq] + BN_EPS);
        float w0 = s1 * (w_mlp1[cq * 6 + 3] - w_mlp1[cq * 6 + 0]);
        float w1 = s1 * (w_mlp1[cq * 6 + 4] - w_mlp1[cq * 6 + 1]);
        float w2 = s1 * (w_mlp1[cq * 6 + 5] - w_mlp1[cq * 6 + 2]);
        float b1 = s1 * b_mlp1[cq] + (be1[cq] - m1[cq] * s1);
        #pragma unroll
        for (int p = 0; p < 16; ++p)
            d_Q[(b * NPT + n0 + p) * NC + cq] =
                fmaf(w0, s_x[p], fmaf(w1, s_x[16 + p], fmaf(w2, s_x[32 + p], b1)));
    }
}

// ---------------- fused fenc + down: gather/max/relu then down-proj ----------
__global__ void __launch_bounds__(256) fenc_down_kernel(const float* __restrict__ wd1,
                                                        const float* __restrict__ wd2)
{
    __shared__ __align__(16) float s_fe[8 * NC];   // 4KB
    __shared__ __align__(16) float s_w[32 * 132];  // padded to 132 for float4
    __shared__ float s_part[CDD * 9];
    __shared__ int s_idx[8 * KK];
    int b = blockIdx.y, n0 = blockIdx.x * 8, tid = threadIdx.x;

    for (int i = tid; i < 8 * KK; i += 256)
        s_idx[i] = d_idx[(b * NPT + n0) * KK + i] * NC;   // pre-scaled
    for (int i = tid; i < 32 * NC; i += 256) {
        int o = i >> 7, c = i & 127;
        float w = (o < 16) ? wd1[o * NC + c] : wd2[(o - 16) * NC + c];
        s_w[o * 132 + c] = w;
    }
    __syncthreads();

    // ---- gather phase: 4 points per thread, 4 independent max chains ----
    {
        int c = tid & 127, ph = tid >> 7;
        const float* Pb = d_P + b * NPT * NC + c;
        float m[4];
        #pragma unroll
        for (int r = 0; r < 4; ++r) m[r] = -1e30f;
        #pragma unroll
        for (int kb = 0; kb < KK; kb += 5) {
            float v[4][5];
            #pragma unroll
            for (int r = 0; r < 4; ++r)
                #pragma unroll
                for (int kk = 0; kk < 5; ++kk)
                    v[r][kk] = Pb[s_idx[(ph * 4 + r) * KK + kb + kk]];
            #pragma unroll
            for (int r = 0; r < 4; ++r)
                #pragma unroll
                for (int kk = 0; kk < 5; ++kk)
                    m[r] = fmaxf(m[r], v[r][kk]);
        }
        #pragma unroll
        for (int r = 0; r < 4; ++r) {
            int p = ph * 4 + r;
            int n = n0 + p;
            float q = d_Q[(b * NPT + n) * NC + c];
            float fe = fmaxf(q + m[r], 0.f);
            s_fe[p * NC + c] = fe;
            d_fenc[(b * NPT + n) * NC + c] = fe;
        }
    }
    __syncthreads();

    // ---- down phase: float4 LDS, same arithmetic order as scalar ----
    int o = tid & 31, p = tid >> 5;
    const float4* wr = (const float4*)(s_w + o * 132);
    const float4* fr = (const float4*)(s_fe + p * NC);
    float a = 0.f;
    #pragma unroll 8
    for (int c4 = 0; c4 < 32; ++c4) {
        float4 w4 = wr[c4];
        float4 f4 = fr[c4];
        a = fmaf(w4.x, f4.x, a);
        a = fmaf(w4.y, f4.y, a);
        a = fmaf(w4.z, f4.z, a);
        a = fmaf(w4.w, f4.w, a);
    }
    a = fmaxf(a, 0.f);
    int n = n0 + p;
    if (o < 16) {
        d_f1[(b * NPT + n) * CDD + o] = a;
        if (b == 0) s_part[o * 9 + p] = a;
    } else {
        d_f2[(b * NPT + n) * CDD + (o - 16)] = a;
    }
    if (b == 0) {
        float v = (o >= 16) ? a : 0.f;
        #pragma unroll
        for (int off = 16; off > 0; off >>= 1)
            v += __shfl_down_sync(0xffffffffu, v, off);
        if (o == 0) d_fsp[n] = v * (1.f / 16.f);
        __syncthreads();
        if (tid < CDD) {
            float s = 0.f;
            #pragma unroll
            for (int p2 = 0; p2 < 8; ++p2) s += s_part[tid * 9 + p2];
            d_fchpart[blockIdx.x * CDD + tid] = s;
        }
    }
}

// ---------------- final: vectorized fch reduce, cross-term, up-proj, mish ----
__global__ void __launch_bounds__(256) final_kernel(float* __restrict__ out,
                                                    const float* __restrict__ w_up,
                                                    const float* __restrict__ b_up,
                                                    const float* __restrict__ gu,
                                                    const float* __restrict__ beu,
                                                    const float* __restrict__ mu,
                                                    const float* __restrict__ vu)
{
    __shared__ float s_v[16 * 17];
    __shared__ float s_o[128 * 17];
    __shared__ float s_red[CDD][68];
    __shared__ float s_fch[CDD];
    int b = blockIdx.y, n0 = blockIdx.x * 16, tid = threadIdx.x;

    // inline deterministic f_channel reduction, float4 loads (identical in
    // every block -> deterministic). Thread = (o-quad, 8 block-rows).
    {
        int q = tid & 3, ch = tid >> 2;          // quad 0..3, chunk 0..63
        const float4* fp4 = (const float4*)d_fchpart;  // [512][4]
        float4 acc = make_float4(0.f, 0.f, 0.f, 0.f);
        #pragma unroll
        for (int i = 0; i < 8; ++i) {
            float4 v = fp4[(ch * 8 + i) * 4 + q];
            acc.x += v.x; acc.y += v.y; acc.z += v.z; acc.w += v.w;
        }
        s_red[q * 4 + 0][ch] = acc.x;
        s_red[q * 4 + 1][ch] = acc.y;
        s_red[q * 4 + 2][ch] = acc.z;
        s_red[q * 4 + 3][ch] = acc.w;
    }
    __syncthreads();
    if (tid < CDD) {
        float sum = 0.f;
        #pragma unroll 8
        for (int c2 = 0; c2 < 64; ++c2) sum += s_red[tid][c2];
        s_fch[tid] = sum * (1.f / (float)NPT);
    }
    __syncthreads();

    {
        int o = tid & 15, p = tid >> 4;    // 256 threads = 16x16 exactly
        int n = n0 + p;
        float f1v = d_f1[(b * NPT + n) * CDD + o];
        float f2v = d_f2[(b * NPT + n) * CDD + o];
        float cross = sqrtf(fmaf(s_fch[o], d_fsp[n], 1e-12f));
        s_v[o * 17 + p] = cross + f1v + f2v;
    }
    __syncthreads();

    int c = tid & 127, ph = tid >> 7;
    float su = gu[c] * rsqrtf(vu[c] + BN_EPS);
    float w16[16];
    #pragma unroll
    for (int o = 0; o < 16; ++o) w16[o] = su * w_up[c * CDD + o];
    float bup = su * b_up[c] + (beu[c] - mu[c] * su);

    #pragma unroll
    for (int p = ph * 8; p < ph * 8 + 8; ++p) {
        float a = bup;
        #pragma unroll
        for (int o = 0; o < 16; ++o) a = fmaf(w16[o], s_v[o * 17 + p], a);
        float U = fmaxf(a, 0.f);
        float fe = d_fenc[(b * NPT + n0 + p) * NC + c];
        float x = fe - U;
        float e = __expf(x);
        float u = fmaf(e, e, e + e);            // e^2 + 2e
        float t = (x > 30.f) ? 1.f : __fdividef(u, u + 2.f);
        s_o[c * 17 + p] = x * t;
    }
    __syncthreads();

    for (int i = tid; i < 128 * 16; i += 256) {
        int cc = i >> 4, p = i & 15;
        out[b * NC * NPT + cc * NPT + n0 + p] = s_o[cc * 17 + p];
    }
}

// ---------------- launch ----------------
extern "C" void kernel_launch(void* const* d_in, const int* in_sizes, int n_in,
                              void* d_out, int out_size)
{
    const float* xyz      = (const float*)d_in[0];
    const float* features = (const float*)d_in[1];
    const float* w_mlp1   = (const float*)d_in[2];
    const float* b_mlp1   = (const float*)d_in[3];
    const float* g1       = (const float*)d_in[4];
    const float* be1      = (const float*)d_in[5];
    const float* m1       = (const float*)d_in[6];
    const float* v1       = (const float*)d_in[7];
    const float* w_mlp2   = (const float*)d_in[8];
    const float* b_mlp2   = (const float*)d_in[9];
    const float* g2       = (const float*)d_in[10];
    const float* be2      = (const float*)d_in[11];
    const float* m2       = (const float*)d_in[12];
    const float* v2       = (const float*)d_in[13];
    const float* w_down1  = (const float*)d_in[14];
    const float* w_down2  = (const float*)d_in[15];
    const float* w_up     = (const float*)d_in[16];
    const float* b_up     = (const float*)d_in[17];
    const float* gu       = (const float*)d_in[18];
    const float* beu      = (const float*)d_in[19];
    const float* mu       = (const float*)d_in[20];
    const float* vu       = (const float*)d_in[21];
    // d_in[22] = k (always 20 for this problem; compiled in)

    knn_kernel<<<dim3(NPT / 16, NB), 256>>>(xyz);
    pq_kernel<<<dim3(NPT / 16, NB), 128>>>(xyz, features,
                                           w_mlp1, b_mlp1, g1, be1, m1, v1,
                                           w_mlp2, b_mlp2, g2, be2, m2, v2);
    fenc_down_kernel<<<dim3(NPT / 8, NB), 256>>>(w_down1, w_down2);
    final_kernel<<<dim3(NPT / 16, NB), 256>>>((float*)d_out,
                                              w_up, b_up, gu, beu, mu, vu);
}

// round 17
// speedup vs baseline: 1.2580x; 1.0579x over previous
#include <cuda_runtime.h>
#include <math.h>

#define BN_EPS 1e-5f
#define NB 2
#define NC 128
#define NPT 4096
#define KK 20
#define CHH 64
#define CDD 16

// ---------------- device scratch (no allocations allowed) ----------------
__device__ int   d_idx[NB * NPT * KK];
__device__ float d_P[NB * NPT * NC];       // [b][n][c]  c<64: xyz-half, c>=64: feat-half
__device__ float d_Q[NB * NPT * NC];
__device__ float d_fenc[NB * NPT * NC];    // [b][n][c]
__device__ float d_f1[NB * NPT * CDD];     // [b][n][o]
__device__ float d_f2[NB * NPT * CDD];
__device__ float d_fsp[NPT];
__device__ float d_fchpart[512 * CDD];

// ---------------- fused KNN + PQ: heterogeneous grid ----------------
// Blocks x<256 run the (proven R14) knn body: latency-bound on the warp
// insertion chain, issue <30%. Blocks x>=256 run pq: FMA/LDS-throughput
// bound. Co-residency on each SM lets pq fill knn's idle issue slots.
// pq is widened to 32 points/block (256 thr) halving weight-staging per point.
__global__ void __launch_bounds__(256) knnpq_kernel(
    const float* __restrict__ xyz,
    const float* __restrict__ features,
    const float* __restrict__ w_mlp1, const float* __restrict__ b_mlp1,
    const float* __restrict__ g1, const float* __restrict__ be1,
    const float* __restrict__ m1, const float* __restrict__ v1,
    const float* __restrict__ w_mlp2, const float* __restrict__ b_mlp2,
    const float* __restrict__ g2, const float* __restrict__ be2,
    const float* __restrict__ m2, const float* __restrict__ v2)
{
    extern __shared__ __align__(16) char smem_raw[];
    int b = blockIdx.y;
    int tid = threadIdx.x;

    if (blockIdx.x < 256) {
        // ================= KNN body (R14, unchanged semantics) =============
        float2* sxy = (float2*)smem_raw;              // 32KB
        float*  szz = (float*)(smem_raw + 32768);     // 16KB

        const float* base = xyz + b * 3 * NPT;
        for (int i = tid; i < NPT; i += 256) {
            sxy[i] = make_float2(base[i], base[NPT + i]);
            szz[i] = base[2 * NPT + i];
        }
        __syncthreads();

        int warp = tid >> 5;
        int lane = tid & 31;
        const unsigned FULL = 0xffffffffu;
        int n0 = (blockIdx.x * 8 + warp) * 2;

        float xn[2], yn[2], zn[2], ld[2], worst[2];
        int   lj[2];
        #pragma unroll
        for (int r = 0; r < 2; ++r) {
            float2 c = sxy[n0 + r];
            xn[r] = c.x; yn[r] = c.y; zn[r] = szz[n0 + r];
            ld[r] = 1e30f; lj[r] = 0; worst[r] = 1e30f;
        }

        for (int j0 = 0; j0 < NPT; j0 += 32) {
            float2 pxy = sxy[j0 + lane];
            float  pz  = szz[j0 + lane];
            float d[2];
            #pragma unroll
            for (int r = 0; r < 2; ++r) {
                float dx = pxy.x - xn[r];
                float dy = pxy.y - yn[r];
                float dz = pz    - zn[r];
                d[r] = fmaf(dx, dx, fmaf(dy, dy, dz * dz));
            }
            #pragma unroll
            for (int r = 0; r < 2; ++r) {
                unsigned mask = __ballot_sync(FULL, d[r] < worst[r]);
                if (mask) {
                    do {
                        int src = __ffs(mask) - 1;
                        mask &= mask - 1;
                        float v = __shfl_sync(FULL, d[r], src);
                        bool gt = (lane < KK) && (ld[r] > v);
                        unsigned gm = __ballot_sync(FULL, gt);
                        if (gm) {                       // v < current 20th
                            int pos = __ffs(gm) - 1;
                            float ud = __shfl_up_sync(FULL, ld[r], 1);
                            int   uj = __shfl_up_sync(FULL, lj[r], 1);
                            if (lane > pos && lane < KK) { ld[r] = ud; lj[r] = uj; }
                            if (lane == pos)             { ld[r] = v;  lj[r] = j0 + src; }
                        }
                    } while (mask);
                    worst[r] = __shfl_sync(FULL, ld[r], KK - 1);
                }
            }
        }

        #pragma unroll
        for (int r = 0; r < 2; ++r)
            if (lane < KK)
                d_idx[(b * NPT + n0 + r) * KK + lane] = lj[r];
    } else {
        // ================= PQ body: 32 points, 256 threads =================
        float* s_f = (float*)smem_raw;                 // [128 j][32 p] 16KB
        float* s_w = (float*)(smem_raw + 16384);       // [64 jl][129]  33KB
        __shared__ float s_x[3 * 32];
        __shared__ float s_s2[64];

        int n0 = (blockIdx.x - 256) * 32;

        for (int i = tid; i < NC * 32; i += 256) {
            int j = i >> 5, p = i & 31;
            s_f[i] = features[b * NC * NPT + j * NPT + n0 + p];
        }
        if (tid < 96) {
            int j = tid >> 5, p = tid & 31;
            s_x[tid] = xyz[b * 3 * NPT + j * NPT + n0 + p];
        }
        if (tid < 64)
            s_s2[tid] = g2[tid] * rsqrtf(v2[tid] + BN_EPS);

        float acc[16];
        #pragma unroll
        for (int p = 0; p < 16; ++p) acc[p] = 0.f;
        int cout = tid & 127;
        int ph = tid >> 7;          // point half: 0 -> p 0..15, 1 -> p 16..31
        int pb = ph * 16;

        for (int jc = 0; jc < NC; jc += 64) {
            __syncthreads();
            for (int i = tid; i < 64 * 128; i += 256) {
                int jl = i & 63, co = i >> 6;
                int cc = (co < 64) ? co : (co - 64);
                float wa = w_mlp2[cc * 256 + jc + jl];
                float w;
                if (co < 64) {
                    w = s_s2[cc] * wa;
                } else {
                    float wb = w_mlp2[cc * 256 + 128 + jc + jl];
                    w = s_s2[cc] * (wb - wa);
                }
                s_w[jl * 129 + co] = w;
            }
            __syncthreads();
            #pragma unroll 4
            for (int jl = 0; jl < 64; ++jl) {
                float w = s_w[jl * 129 + cout];
                const float4* f4 = (const float4*)(s_f + (jc + jl) * 32 + pb);
                float fv[16];
                *(float4*)(fv + 0)  = f4[0];
                *(float4*)(fv + 4)  = f4[1];
                *(float4*)(fv + 8)  = f4[2];
                *(float4*)(fv + 12) = f4[3];
                #pragma unroll
                for (int p = 0; p < 16; ++p) acc[p] = fmaf(w, fv[p], acc[p]);
            }
        }

        if (cout < 64) {
            #pragma unroll
            for (int p = 0; p < 16; ++p)
                d_P[(b * NPT + n0 + pb + p) * NC + 64 + cout] = acc[p];
            float s1 = g1[cout] * rsqrtf(v1[cout] + BN_EPS);
            float w0 = s1 * w_mlp1[cout * 6 + 0];
            float w1 = s1 * w_mlp1[cout * 6 + 1];
            float w2 = s1 * w_mlp1[cout * 6 + 2];
            #pragma unroll
            for (int p = 0; p < 16; ++p)
                d_P[(b * NPT + n0 + pb + p) * NC + cout] =
                    fmaf(w0, s_x[pb + p], fmaf(w1, s_x[32 + pb + p], w2 * s_x[64 + pb + p]));
        } else {
            int cq = cout - 64;
            float s2v = s_s2[cq];
            float bb = s2v * b_mlp2[cq] + (be2[cq] - m2[cq] * s2v);
            #pragma unroll
            for (int p = 0; p < 16; ++p)
                d_Q[(b * NPT + n0 + pb + p) * NC + 64 + cq] = acc[p] + bb;
            float s1 = g1[cq] * rsqrtf(v1[cq] + BN_EPS);
            float w0 = s1 * (w_mlp1[cq * 6 + 3] - w_mlp1[cq * 6 + 0]);
            float w1 = s1 * (w_mlp1[cq * 6 + 4] - w_mlp1[cq * 6 + 1]);
            float w2 = s1 * (w_mlp1[cq * 6 + 5] - w_mlp1[cq * 6 + 2]);
            float b1 = s1 * b_mlp1[cq] + (be1[cq] - m1[cq] * s1);
            #pragma unroll
            for (int p = 0; p < 16; ++p)
                d_Q[(b * NPT + n0 + pb + p) * NC + cq] =
                    fmaf(w0, s_x[pb + p], fmaf(w1, s_x[32 + pb + p], fmaf(w2, s_x[64 + pb + p], b1)));
        }
    }
}

// ---------------- fused fenc + down: gather/max/relu then down-proj ----------
__global__ void __launch_bounds__(256) fenc_down_kernel(const float* __restrict__ wd1,
                                                        const float* __restrict__ wd2)
{
    __shared__ __align__(16) float s_fe[8 * NC];   // 4KB
    __shared__ __align__(16) float s_w[32 * 132];  // padded to 132 for float4
    __shared__ float s_part[CDD * 9];
    __shared__ int s_idx[8 * KK];
    int b = blockIdx.y, n0 = blockIdx.x * 8, tid = threadIdx.x;

    for (int i = tid; i < 8 * KK; i += 256)
        s_idx[i] = d_idx[(b * NPT + n0) * KK + i] * NC;   // pre-scaled
    for (int i = tid; i < 32 * NC; i += 256) {
        int o = i >> 7, c = i & 127;
        float w = (o < 16) ? wd1[o * NC + c] : wd2[(o - 16) * NC + c];
        s_w[o * 132 + c] = w;
    }
    __syncthreads();

    // ---- gather phase: 4 points per thread, 4 independent max chains ----
    {
        int c = tid & 127, ph = tid >> 7;
        const float* Pb = d_P + b * NPT * NC + c;
        float m[4];
        #pragma unroll
        for (int r = 0; r < 4; ++r) m[r] = -1e30f;
        #pragma unroll
        for (int kb = 0; kb < KK; kb += 5) {
            float v[4][5];
            #pragma unroll
            for (int r = 0; r < 4; ++r)
                #pragma unroll
                for (int kk = 0; kk < 5; ++kk)
                    v[r][kk] = Pb[s_idx[(ph * 4 + r) * KK + kb + kk]];
            #pragma unroll
            for (int r = 0; r < 4; ++r)
                #pragma unroll
                for (int kk = 0; kk < 5; ++kk)
                    m[r] = fmaxf(m[r], v[r][kk]);
        }
        #pragma unroll
        for (int r = 0; r < 4; ++r) {
            int p = ph * 4 + r;
            int n = n0 + p;
            float q = d_Q[(b * NPT + n) * NC + c];
            float fe = fmaxf(q + m[r], 0.f);
            s_fe[p * NC + c] = fe;
            d_fenc[(b * NPT + n) * NC + c] = fe;
        }
    }
    __syncthreads();

    // ---- down phase: float4 LDS, same arithmetic order as scalar ----
    int o = tid & 31, p = tid >> 5;
    const float4* wr = (const float4*)(s_w + o * 132);
    const float4* fr = (const float4*)(s_fe + p * NC);
    float a = 0.f;
    #pragma unroll 8
    for (int c4 = 0; c4 < 32; ++c4) {
        float4 w4 = wr[c4];
        float4 f4 = fr[c4];
        a = fmaf(w4.x, f4.x, a);
        a = fmaf(w4.y, f4.y, a);
        a = fmaf(w4.z, f4.z, a);
        a = fmaf(w4.w, f4.w, a);
    }
    a = fmaxf(a, 0.f);
    int n = n0 + p;
    if (o < 16) {
        d_f1[(b * NPT + n) * CDD + o] = a;
        if (b == 0) s_part[o * 9 + p] = a;
    } else {
        d_f2[(b * NPT + n) * CDD + (o - 16)] = a;
    }
    if (b == 0) {
        float v = (o >= 16) ? a : 0.f;
        #pragma unroll
        for (int off = 16; off > 0; off >>= 1)
            v += __shfl_down_sync(0xffffffffu, v, off);
        if (o == 0) d_fsp[n] = v * (1.f / 16.f);
        __syncthreads();
        if (tid < CDD) {
            float s = 0.f;
            #pragma unroll
            for (int p2 = 0; p2 < 8; ++p2) s += s_part[tid * 9 + p2];
            d_fchpart[blockIdx.x * CDD + tid] = s;
        }
    }
}

// ---------------- final: vectorized fch reduce, cross-term, up-proj, mish ----
__global__ void __launch_bounds__(256) final_kernel(float* __restrict__ out,
                                                    const float* __restrict__ w_up,
                                                    const float* __restrict__ b_up,
                                                    const float* __restrict__ gu,
                                                    const float* __restrict__ beu,
                                                    const float* __restrict__ mu,
                                                    const float* __restrict__ vu)
{
    __shared__ float s_v[16 * 17];
    __shared__ float s_o[128 * 17];
    __shared__ float s_red[CDD][68];
    __shared__ float s_fch[CDD];
    int b = blockIdx.y, n0 = blockIdx.x * 16, tid = threadIdx.x;

    // inline deterministic f_channel reduction, float4 loads (identical in
    // every block -> deterministic). Thread = (o-quad, 8 block-rows).
    {
        int q = tid & 3, ch = tid >> 2;          // quad 0..3, chunk 0..63
        const float4* fp4 = (const float4*)d_fchpart;  // [512][4]
        float4 acc = make_float4(0.f, 0.f, 0.f, 0.f);
        #pragma unroll
        for (int i = 0; i < 8; ++i) {
            float4 v = fp4[(ch * 8 + i) * 4 + q];
            acc.x += v.x; acc.y += v.y; acc.z += v.z; acc.w += v.w;
        }
        s_red[q * 4 + 0][ch] = acc.x;
        s_red[q * 4 + 1][ch] = acc.y;
        s_red[q * 4 + 2][ch] = acc.z;
        s_red[q * 4 + 3][ch] = acc.w;
    }
    __syncthreads();
    if (tid < CDD) {
        float sum = 0.f;
        #pragma unroll 8
        for (int c2 = 0; c2 < 64; ++c2) sum += s_red[tid][c2];
        s_fch[tid] = sum * (1.f / (float)NPT);
    }
    __syncthreads();

    {
        int o = tid & 15, p = tid >> 4;    // 256 threads = 16x16 exactly
        int n = n0 + p;
        float f1v = d_f1[(b * NPT + n) * CDD + o];
        float f2v = d_f2[(b * NPT + n) * CDD + o];
        float cross = sqrtf(fmaf(s_fch[o], d_fsp[n], 1e-12f));
        s_v[o * 17 + p] = cross + f1v + f2v;
    }
    __syncthreads();

    int c = tid & 127, ph = tid >> 7;
    float su = gu[c] * rsqrtf(vu[c] + BN_EPS);
    float w16[16];
    #pragma unroll
    for (int o = 0; o < 16; ++o) w16[o] = su * w_up[c * CDD + o];
    float bup = su * b_up[c] + (beu[c] - mu[c] * su);

    #pragma unroll
    for (int p = ph * 8; p < ph * 8 + 8; ++p) {
        float a = bup;
        #pragma unroll
        for (int o = 0; o < 16; ++o) a = fmaf(w16[o], s_v[o * 17 + p], a);
        float U = fmaxf(a, 0.f);
        float fe = d_fenc[(b * NPT + n0 + p) * NC + c];
        float x = fe - U;
        float e = __expf(x);
        float u = fmaf(e, e, e + e);            // e^2 + 2e
        float t = (x > 30.f) ? 1.f : __fdividef(u, u + 2.f);
        s_o[c * 17 + p] = x * t;
    }
    __syncthreads();

    for (int i = tid; i < 128 * 16; i += 256) {
        int cc = i >> 4, p = i & 15;
        out[b * NC * NPT + cc * NPT + n0 + p] = s_o[cc * 17 + p];
    }
}

// ---------------- launch ----------------
extern "C" void kernel_launch(void* const* d_in, const int* in_sizes, int n_in,
                              void* d_out, int out_size)
{
    const float* xyz      = (const float*)d_in[0];
    const float* features = (const float*)d_in[1];
    const float* w_mlp1   = (const float*)d_in[2];
    const float* b_mlp1   = (const float*)d_in[3];
    const float* g1       = (const float*)d_in[4];
    const float* be1      = (const float*)d_in[5];
    const float* m1       = (const float*)d_in[6];
    const float* v1       = (const float*)d_in[7];
    const float* w_mlp2   = (const float*)d_in[8];
    const float* b_mlp2   = (const float*)d_in[9];
    const float* g2       = (const float*)d_in[10];
    const float* be2      = (const float*)d_in[11];
    const float* m2       = (const float*)d_in[12];
    const float* v2       = (const float*)d_in[13];
    const float* w_down1  = (const float*)d_in[14];
    const float* w_down2  = (const float*)d_in[15];
    const float* w_up     = (const float*)d_in[16];
    const float* b_up     = (const float*)d_in[17];
    const float* gu       = (const float*)d_in[18];
    const float* beu      = (const float*)d_in[19];
    const float* mu       = (const float*)d_in[20];
    const float* vu       = (const float*)d_in[21];
    // d_in[22] = k (always 20 for this problem; compiled in)

    // max(knn 48KB, pq 16KB + 64*129*4B) = 49408 bytes dynamic
    const int SMEM = 16384 + 64 * 129 * 4;
    cudaFuncSetAttribute(knnpq_kernel,
                         cudaFuncAttributeMaxDynamicSharedMemorySize, SMEM);

    knnpq_kernel<<<dim3(256 + NPT / 32, NB), 256, SMEM>>>(
        xyz, features,
        w_mlp1, b_mlp1, g1, be1, m1, v1,
        w_mlp2, b_mlp2, g2, be2, m2, v2);
    fenc_down_kernel<<<dim3(NPT / 8, NB), 256>>>(w_down1, w_down2);
    final_kernel<<<dim3(NPT / 16, NB), 256>>>((float*)d_out,
                                              w_up, b_up, gu, beu, mu, vu);
}